// round 5
// baseline (speedup 1.0000x reference)
#include <cuda_runtime.h>
#include <cuda_bf16.h>
#include <cstdint>
#include <cstddef>

#define B_    128
#define T_    512
#define IN_   64
#define H_    1024
#define OUT_  64

#define NCTA     128      // persistent CTAs (all resident in one wave)
#define HCH      8        // H neurons per CTA (NCTA*HCH == H_)
#define KP_REC   512      // fr k-pairs (H_/2)
#define KP_IN    32       // input k-pairs (IN_/2)
#define KP_TOT   (KP_REC + KP_IN)
#define KP_SPLIT 272      // half0: rec [0,272) ; half1: rec [272,512) + 32 input pairs

typedef unsigned long long u64;

// ---------------- static device scratch (no allocation allowed) -------------
__device__ u64   g_frP[2][KP_REC][B_];     // fr state, pair-packed [kpair][b], ping-pong (1 MB)
__device__ u64   g_xP[T_][KP_IN][B_];      // input-proj operand, pair-packed (16 MB)
__device__ float g_WoutT[H_ * OUT_];       // W_out transposed [k][o]
__device__ unsigned g_cnt;                 // grid-barrier monotonic counter

// ---------------- helpers ----------------------------------------------------
static __device__ __forceinline__ u64 pack2(float x, float y) {
    u64 r; asm("mov.b64 %0, {%1,%2};" : "=l"(r) : "f"(x), "f"(y)); return r;
}
static __device__ __forceinline__ float2 unpack2(u64 v) {
    float2 r; asm("mov.b64 {%0,%1}, %2;" : "=f"(r.x), "=f"(r.y) : "l"(v)); return r;
}
// packed fp32x2 FMA: acc += a * b (elementwise on both lanes) — Blackwell FFMA2
static __device__ __forceinline__ void fma2(u64& acc, u64 a, u64 b) {
    asm("fma.rn.f32x2 %0, %1, %2, %0;" : "+l"(acc) : "l"(a), "l"(b));
}
static __device__ __forceinline__ unsigned ld_acq(const unsigned* p) {
    unsigned v;
    asm volatile("ld.acquire.gpu.global.u32 %0, [%1];" : "=r"(v) : "l"(p));
    return v;
}

// ============================================================================
// Prep: pack input projection operand [T][KP_IN][B]
// ============================================================================
__global__ void k_prep_x(const float* __restrict__ inp) {
    int i = blockIdx.x * 256 + threadIdx.x;            // T_*KP_IN*B_ = 2097152
    if (i >= T_ * KP_IN * B_) return;
    int b  = i & 127;
    int kq = (i >> 7) & 31;
    int t  = i >> 12;
    const float* s = inp + ((size_t)b * T_ + t) * IN_ + 2 * kq;
    g_xP[t][kq][b] = pack2(s[0], s[1]);
}

// Prep: fr0 pack, W_out transpose, barrier reset
__global__ void k_prep_misc(const float* __restrict__ fr0,
                            const float* __restrict__ Woutw) {
    int i = blockIdx.x * 256 + threadIdx.x;            // exactly 65536 threads
    {   // fr0 -> g_frP[0] : i = hp*128 + b, hp<512
        int b = i & 127, hp = i >> 7;
        const float* s = fr0 + (size_t)b * H_ + 2 * hp;
        g_frP[0][hp][b] = pack2(s[0], s[1]);
    }
    {   // W_out^T : i = k*64 + o, k<1024
        int o = i & 63, k = i >> 6;
        g_WoutT[(size_t)k * OUT_ + o] = Woutw[(size_t)o * H_ + k];
    }
    if (i == 0) g_cnt = 0u;
}

// ============================================================================
// Persistent recurrent loop
// ============================================================================
__global__ void __launch_bounds__(256, 1)
k_rnn(const float* __restrict__ noise,
      const float* __restrict__ Winw,  const float* __restrict__ Winb,
      const float* __restrict__ Wrecw, const float* __restrict__ Wrecb,
      const float* __restrict__ fr0,
      float* __restrict__ out_rates)
{
    __shared__ __align__(16) u64    sW[KP_TOT][HCH];   // 34816 B
    __shared__ __align__(16) float2 sRed[B_][HCH];     // 8192 B
    __shared__ float sB[HCH];

    const int tid = threadIdx.x;
    const int c   = blockIdx.x;
    const int h0  = c * HCH;

    // Stage pair-packed weight slice (once per launch)
    for (int i = tid; i < KP_TOT * HCH; i += 256) {
        int j = i & 7, kp = i >> 3;
        if (kp < KP_REC) {
            const float* s = Wrecw + (size_t)(h0 + j) * H_ + 2 * kp;
            sW[kp][j] = pack2(s[0], s[1]);
        } else {
            int kq = kp - KP_REC;
            const float* s = Winw + (size_t)(h0 + j) * IN_ + 2 * kq;
            sW[kp][j] = pack2(s[0], s[1]);
        }
    }
    if (tid < HCH) sB[tid] = Winb[h0 + tid] + Wrecb[h0 + tid];
    __syncthreads();

    const int b    = tid & 127;
    const int half = tid >> 7;

    // half0 keeps this CTA's fr slice (batch b, h0..h0+7) in registers
    float frloc[HCH];
    if (!half) {
        #pragma unroll
        for (int j = 0; j < HCH; ++j)
            frloc[j] = fr0[(size_t)b * H_ + h0 + j];
    }

    for (int t = 0; t < T_; ++t) {
        const u64* cur = &g_frP[t & 1][0][0];
        u64*       nxt = &g_frP[(t + 1) & 1][0][0];

        u64 acc[HCH];
        #pragma unroll
        for (int j = 0; j < HCH; ++j) acc[j] = 0ull;

        const int kp0 = half ? KP_SPLIT : 0;
        const int kp1 = half ? KP_REC   : KP_SPLIT;

        #pragma unroll 8
        for (int kp = kp0; kp < kp1; ++kp) {
            u64 fr2 = __ldcg(cur + (size_t)kp * B_ + b);
            const ulonglong2* w = reinterpret_cast<const ulonglong2*>(&sW[kp][0]);
            ulonglong2 w01 = w[0], w23 = w[1], w45 = w[2], w67 = w[3];
            fma2(acc[0], fr2, w01.x); fma2(acc[1], fr2, w01.y);
            fma2(acc[2], fr2, w23.x); fma2(acc[3], fr2, w23.y);
            fma2(acc[4], fr2, w45.x); fma2(acc[5], fr2, w45.y);
            fma2(acc[6], fr2, w67.x); fma2(acc[7], fr2, w67.y);
        }

        if (half) {
            // input-projection k-pairs
            const u64* xp = &g_xP[t][0][b];
            #pragma unroll 8
            for (int kq = 0; kq < KP_IN; ++kq) {
                u64 x2 = __ldcg(xp + (size_t)kq * B_);
                const ulonglong2* w = reinterpret_cast<const ulonglong2*>(&sW[KP_REC + kq][0]);
                ulonglong2 w01 = w[0], w23 = w[1], w45 = w[2], w67 = w[3];
                fma2(acc[0], x2, w01.x); fma2(acc[1], x2, w01.y);
                fma2(acc[2], x2, w23.x); fma2(acc[3], x2, w23.y);
                fma2(acc[4], x2, w45.x); fma2(acc[5], x2, w45.y);
                fma2(acc[6], x2, w67.x); fma2(acc[7], x2, w67.y);
            }
            #pragma unroll
            for (int j = 0; j < HCH; ++j) sRed[b][j] = unpack2(acc[j]);
        }
        __syncthreads();

        if (!half) {
            const float4* np = reinterpret_cast<const float4*>(
                noise + (((size_t)t * B_ + b) * H_ + h0));
            float4 n0 = np[0];
            float4 n1 = np[1];
            float nn[8] = {n0.x, n0.y, n0.z, n0.w, n1.x, n1.y, n1.z, n1.w};

            float fn[HCH];
            #pragma unroll
            for (int j = 0; j < HCH; ++j) {
                float2 a = unpack2(acc[j]);
                float2 r = sRed[b][j];
                float pre = (a.x + a.y) + (r.x + r.y) + sB[j] + nn[j];
                fn[j] = 0.9f * frloc[j] + 0.1f * tanhf(pre);
                frloc[j] = fn[j];
            }
            #pragma unroll
            for (int p = 0; p < HCH / 2; ++p)
                __stcg(nxt + (size_t)(h0 / 2 + p) * B_ + b, pack2(fn[2*p], fn[2*p+1]));

            float4* rp = reinterpret_cast<float4*>(
                out_rates + (((size_t)b * T_ + t) * H_ + h0));
            rp[0] = make_float4(fn[0], fn[1], fn[2], fn[3]);
            rp[1] = make_float4(fn[4], fn[5], fn[6], fn[7]);
        }

        // ---- grid barrier ----
        if (t < T_ - 1) {
            __threadfence();
            __syncthreads();
            if (tid == 0) {
                atomicAdd(&g_cnt, 1u);
                unsigned target = (unsigned)NCTA * (unsigned)(t + 1);
                while (ld_acq(&g_cnt) < target) { }
            }
            __syncthreads();
        }
    }
}

// ============================================================================
// preds[b][t] = sigmoid(fr_{t-1} @ Wout^T + b);  fr_{-1} = fr0
// 4 (b,t) rows per 256-thread block
// ============================================================================
__global__ void __launch_bounds__(256)
k_preds(const float* __restrict__ fr0,
        const float* __restrict__ Woutb,
        const float* __restrict__ rates,
        float* __restrict__ preds)
{
    __shared__ __align__(16) float sFr[4][H_];         // 16 KB

    const int tid = threadIdx.x;
    const int r   = tid >> 6;       // 0..3
    const int o   = tid & 63;
    const int row0 = blockIdx.x * 4;

    // cooperative load of 4 fr rows
    for (int i = tid; i < 4 * H_; i += 256) {
        int rr = i >> 10, k = i & (H_ - 1);
        int row = row0 + rr;
        int bb = row >> 9;          // row / T_
        int tt = row & (T_ - 1);    // row % T_
        const float* src = (tt == 0)
            ? (fr0 + (size_t)bb * H_ + k)
            : (rates + ((size_t)bb * T_ + (tt - 1)) * H_ + k);
        sFr[rr][k] = src[k - k + 0] ; // plain load
    }
    __syncthreads();

    float acc = Woutb[o];
    const float* wt = g_WoutT + o;
    #pragma unroll 8
    for (int k = 0; k < H_; ++k)
        acc = fmaf(sFr[r][k], __ldg(wt + (size_t)k * OUT_), acc);

    float sig = 1.0f / (1.0f + __expf(-acc));
    int row = row0 + r;
    preds[(size_t)row * OUT_ + o] = sig;
}

// ============================================================================
extern "C" void kernel_launch(void* const* d_in, const int* in_sizes, int n_in,
                              void* d_out, int out_size) {
    (void)in_sizes; (void)n_in; (void)out_size;
    const float* inp   = (const float*)d_in[0];
    const float* fr0   = (const float*)d_in[1];
    const float* noise = (const float*)d_in[2];
    const float* Winw  = (const float*)d_in[3];
    const float* Winb  = (const float*)d_in[4];
    const float* Wrecw = (const float*)d_in[5];
    const float* Wrecb = (const float*)d_in[6];
    const float* Woutw = (const float*)d_in[7];
    const float* Woutb = (const float*)d_in[8];

    float* out   = (float*)d_out;
    float* preds = out;                                   // [B,T,OUT]
    float* rates = out + (size_t)B_ * T_ * OUT_;          // [B,T,H]

    k_prep_x<<<(T_ * KP_IN * B_) / 256, 256>>>(inp);
    k_prep_misc<<<(H_ / 2 * B_) / 256, 256>>>(fr0, Woutw);
    k_rnn<<<NCTA, 256>>>(noise, Winw, Winb, Wrecw, Wrecb, fr0, rates);
    k_preds<<<(B_ * T_) / 4, 256>>>(fr0, Woutb, rates, preds);
}

// round 6
// speedup vs baseline: 1.3425x; 1.3425x over previous
#include <cuda_runtime.h>
#include <cuda_bf16.h>
#include <cstdint>
#include <cstddef>

#define B_    128
#define T_    512
#define IN_   64
#define H_    1024
#define OUT_  64

#define NCTA   128           // 4 b-groups x 32 h-groups
#define KP_REC 512           // recurrent k-pairs
#define KP_IN  32            // input k-pairs
#define KP_TOT (KP_REC + KP_IN)

#define SW_PITCH   34        // u64 pitch for sW rows (pad: 16B-aligned, bank-spread)
#define SRED_PITCH 33        // float pitch for reduction rows (conflict-free)
#define SW_BYTES   (KP_TOT * SW_PITCH * 8)            // 147968
#define SRED_BYTES (8 * 32 * SRED_PITCH * 4)          // 33792
#define SMEM_RNN   (SW_BYTES + SRED_BYTES + 128)      // 181888

typedef unsigned long long u64;

// ---------------- static device scratch --------------------------------------
__device__ u64   g_frP[2][KP_REC][B_];     // fr state pair-packed [kp][b], ping-pong
__device__ u64   g_xP[T_][KP_IN][B_];      // input-proj operand pair-packed
__device__ u64   g_WoutP[KP_REC * OUT_];   // W_out pair-packed [kp][o]
__device__ unsigned g_arrive;              // barrier arrival counter (monotonic)
__device__ unsigned g_epoch;               // barrier epoch (released by last arriver)

// ---------------- helpers -----------------------------------------------------
static __device__ __forceinline__ u64 pack2(float x, float y) {
    u64 r; asm("mov.b64 %0, {%1,%2};" : "=l"(r) : "f"(x), "f"(y)); return r;
}
static __device__ __forceinline__ float2 unpack2(u64 v) {
    float2 r; asm("mov.b64 {%0,%1}, %2;" : "=f"(r.x), "=f"(r.y) : "l"(v)); return r;
}
// packed fp32x2 FMA (Blackwell FFMA2): acc += a*b on both lanes
static __device__ __forceinline__ void fma2(u64& acc, u64 a, u64 b) {
    asm("fma.rn.f32x2 %0, %1, %2, %0;" : "+l"(acc) : "l"(a), "l"(b));
}
static __device__ __forceinline__ unsigned ld_acq(const unsigned* p) {
    unsigned v;
    asm volatile("ld.acquire.gpu.global.u32 %0, [%1];" : "=r"(v) : "l"(p));
    return v;
}
static __device__ __forceinline__ void st_rel(unsigned* p, unsigned v) {
    asm volatile("st.release.gpu.global.u32 [%0], %1;" :: "l"(p), "r"(v) : "memory");
}

// ============================================================================
// Prep: pack input-projection operand [T][KP_IN][B]
// ============================================================================
__global__ void k_prep_x(const float* __restrict__ inp) {
    int i = blockIdx.x * 256 + threadIdx.x;            // T_*KP_IN*B_ = 2097152
    if (i >= T_ * KP_IN * B_) return;
    int b  = i & 127;
    int kq = (i >> 7) & 31;
    int t  = i >> 12;
    const float* s = inp + ((size_t)b * T_ + t) * IN_ + 2 * kq;
    g_xP[t][kq][b] = pack2(s[0], s[1]);
}

// Prep: fr0 pack, W_out pair-pack, barrier reset
__global__ void k_prep_misc(const float* __restrict__ fr0,
                            const float* __restrict__ Woutw) {
    int i = blockIdx.x * 256 + threadIdx.x;            // 65536 threads
    {   // fr0 -> g_frP[0]
        int b = i & 127, hp = i >> 7;                  // hp < 512
        const float* s = fr0 + (size_t)b * H_ + 2 * hp;
        g_frP[0][hp][b] = pack2(s[0], s[1]);
    }
    if (i < KP_REC * OUT_) {                           // 32768
        int kp = i & 511, o = i >> 9;                  // lanes: kp fast -> coalesced src
        const float* s = Woutw + (size_t)o * H_ + 2 * kp;
        g_WoutP[(size_t)kp * OUT_ + o] = pack2(s[0], s[1]);
    }
    if (i == 0) { g_arrive = 0u; g_epoch = 0u; }
}

// ============================================================================
// Persistent recurrent loop: CTA = (bg in 0..3) x (hg in 0..31)
// owns 32 batches x 32 hidden units. Thread = (b_local, k-slice kq in 0..7).
// ============================================================================
__global__ void __launch_bounds__(256, 1)
k_rnn(const float* __restrict__ noise,
      const float* __restrict__ Winw,  const float* __restrict__ Winb,
      const float* __restrict__ Wrecw, const float* __restrict__ Wrecb,
      const float* __restrict__ fr0,
      float* __restrict__ out_rates)
{
    extern __shared__ unsigned char smem[];
    u64  (*sW)[SW_PITCH] = reinterpret_cast<u64(*)[SW_PITCH]>(smem);
    float* sRed = reinterpret_cast<float*>(smem + SW_BYTES);
    float* sB   = reinterpret_cast<float*>(smem + SW_BYTES + SRED_BYTES);

    const int tid = threadIdx.x;
    const int bg  = blockIdx.x & 3;
    const int hg  = blockIdx.x >> 2;
    const int h0  = hg * 32;
    const int b0  = bg * 32;

    // ---- stage pair-packed weight slice: sW[kp][h'] (one warp per h' row) ----
    {
        const int lane = tid & 31;
        for (int h = tid >> 5; h < 32; h += 8) {
            const float* wr = Wrecw + (size_t)(h0 + h) * H_;
            for (int kp = lane; kp < KP_REC; kp += 32) {
                float2 v = *reinterpret_cast<const float2*>(wr + 2 * kp);
                sW[kp][h] = pack2(v.x, v.y);
            }
            if (lane < KP_IN) {
                const float* wi = Winw + (size_t)(h0 + h) * IN_;
                float2 v = *reinterpret_cast<const float2*>(wi + 2 * lane);
                sW[KP_REC + lane][h] = pack2(v.x, v.y);
            }
        }
        if (tid < 32) sB[tid] = Winb[h0 + tid] + Wrecb[h0 + tid];
    }

    // ---- epilogue role: thread owns (eb, eh..eh+3), fr kept in registers ----
    const int eb  = tid >> 3;            // local b   (0..31)
    const int eh  = (tid & 7) * 4;       // local h   (0,4,..,28)
    const int ebg = b0 + eb;
    const int ehg = h0 + eh;
    float frloc[4];
    {
        float4 f = *reinterpret_cast<const float4*>(fr0 + (size_t)ebg * H_ + ehg);
        frloc[0] = f.x; frloc[1] = f.y; frloc[2] = f.z; frloc[3] = f.w;
    }
    __syncthreads();

    const int bl    = tid & 31;          // compute-role local b
    const int kq    = tid >> 5;          // compute-role k slice (0..7)
    const int bglob = b0 + bl;

    for (int t = 0; t < T_; ++t) {
        const u64* cur = &g_frP[t & 1][0][0];
        u64*       nxt = &g_frP[(t + 1) & 1][0][0];

        u64 acc[32];
        #pragma unroll
        for (int j = 0; j < 32; ++j) acc[j] = 0ull;

        // recurrent part: 64 k-pairs for this slice
        {
            const u64* p = cur + (size_t)(kq * 64) * B_ + bglob;
            #pragma unroll 4
            for (int i = 0; i < 64; ++i) {
                u64 fr2 = __ldcg(p + (size_t)i * B_);
                const ulonglong2* w =
                    reinterpret_cast<const ulonglong2*>(&sW[kq * 64 + i][0]);
                #pragma unroll
                for (int q = 0; q < 16; ++q) {
                    ulonglong2 ww = w[q];
                    fma2(acc[2 * q],     fr2, ww.x);
                    fma2(acc[2 * q + 1], fr2, ww.y);
                }
            }
        }
        // input-projection part: 4 k-pairs for this slice
        {
            const u64* p = &g_xP[t][kq * 4][0] + bglob;
            #pragma unroll
            for (int i = 0; i < 4; ++i) {
                u64 x2 = __ldcg(p + (size_t)i * B_);
                const ulonglong2* w =
                    reinterpret_cast<const ulonglong2*>(&sW[KP_REC + kq * 4 + i][0]);
                #pragma unroll
                for (int q = 0; q < 16; ++q) {
                    ulonglong2 ww = w[q];
                    fma2(acc[2 * q],     x2, ww.x);
                    fma2(acc[2 * q + 1], x2, ww.y);
                }
            }
        }
        // pair-sum -> reduction smem (conflict-free: bank = (b + h) mod 32)
        {
            float* dst = sRed + ((size_t)kq * 32 + bl) * SRED_PITCH;
            #pragma unroll
            for (int h = 0; h < 32; ++h) {
                float2 v = unpack2(acc[h]);
                dst[h] = v.x + v.y;
            }
        }
        __syncthreads();

        // ---- epilogue: 8-way k reduce, bias+noise, tanh, leaky update -------
        {
            float s0 = 0.f, s1 = 0.f, s2 = 0.f, s3 = 0.f;
            #pragma unroll
            for (int q = 0; q < 8; ++q) {
                const float* src = sRed + ((size_t)q * 32 + eb) * SRED_PITCH + eh;
                s0 += src[0]; s1 += src[1]; s2 += src[2]; s3 += src[3];
            }
            float4 n = *reinterpret_cast<const float4*>(
                noise + ((size_t)t * B_ + ebg) * H_ + ehg);

            frloc[0] = 0.9f * frloc[0] + 0.1f * tanhf(s0 + sB[eh + 0] + n.x);
            frloc[1] = 0.9f * frloc[1] + 0.1f * tanhf(s1 + sB[eh + 1] + n.y);
            frloc[2] = 0.9f * frloc[2] + 0.1f * tanhf(s2 + sB[eh + 2] + n.z);
            frloc[3] = 0.9f * frloc[3] + 0.1f * tanhf(s3 + sB[eh + 3] + n.w);

            const size_t kp0 = (size_t)(ehg >> 1);
            __stcg(nxt + kp0 * B_ + ebg,        pack2(frloc[0], frloc[1]));
            __stcg(nxt + (kp0 + 1) * B_ + ebg,  pack2(frloc[2], frloc[3]));

            *reinterpret_cast<float4*>(
                out_rates + ((size_t)ebg * T_ + t) * H_ + ehg) =
                make_float4(frloc[0], frloc[1], frloc[2], frloc[3]);
        }

        // ---- grid barrier: arrive counter + release epoch, read-only polls --
        if (t < T_ - 1) {
            __threadfence();
            __syncthreads();
            if (tid == 0) {
                unsigned old = atomicAdd(&g_arrive, 1u);
                if (old == (unsigned)(NCTA * (t + 1)) - 1u) {
                    st_rel(&g_epoch, (unsigned)(t + 1));
                } else {
                    while (ld_acq(&g_epoch) < (unsigned)(t + 1)) {}
                }
            }
            __syncthreads();
        }
    }
}

// ============================================================================
// preds: sigmoid(fr_{t-1} @ Wout^T + b). Tiled GEMM: block = 64 rows x 64 outs,
// 16 k-chunks of 32 k-pairs staged in smem, FFMA2 4x4 thread tiles.
// ============================================================================
#define PR_CH   32                     // k-pairs per chunk
#define PR_PITCH 66                    // u64 pitch (16B aligned: 66*8=528)

__global__ void __launch_bounds__(256)
k_preds(const float* __restrict__ fr0,
        const float* __restrict__ Woutb,
        const float* __restrict__ rates,
        float* __restrict__ preds)
{
    __shared__ __align__(16) u64 sFr[PR_CH][PR_PITCH];   // 16896 B
    __shared__ __align__(16) u64 sWo[PR_CH][PR_PITCH];   // 16896 B

    const int tid  = threadIdx.x;
    const int rx   = tid >> 4;          // 0..15 -> rows rx*4..+3
    const int ox   = tid & 15;          // 0..15 -> outs ox*4..+3
    const int row0 = blockIdx.x * 64;

    u64 acc[16];
    #pragma unroll
    for (int j = 0; j < 16; ++j) acc[j] = 0ull;

    for (int c = 0; c < KP_REC / PR_CH; ++c) {
        // stage fr rows (pair-packed, transposed to [kp][row])
        #pragma unroll
        for (int it = 0; it < 4; ++it) {
            int i  = tid + it * 256;                    // < 1024
            int f4 = i & 15, r = i >> 4;
            int row = row0 + r;
            int bb = row >> 9, tt = row & (T_ - 1);
            const float4* src = (tt == 0)
                ? reinterpret_cast<const float4*>(fr0 + (size_t)bb * H_)
                : reinterpret_cast<const float4*>(
                      rates + ((size_t)bb * T_ + (tt - 1)) * H_);
            float4 v = src[c * 16 + f4];
            sFr[f4 * 2][r]     = pack2(v.x, v.y);
            sFr[f4 * 2 + 1][r] = pack2(v.z, v.w);
        }
        // stage W chunk
        #pragma unroll
        for (int it = 0; it < 4; ++it) {
            int i   = tid + it * 256;                   // < 1024
            int u2  = i & 31, kpl = i >> 5;
            ulonglong2 v = *reinterpret_cast<const ulonglong2*>(
                &g_WoutP[(size_t)(c * PR_CH + kpl) * OUT_ + u2 * 2]);
            *reinterpret_cast<ulonglong2*>(&sWo[kpl][u2 * 2]) = v;
        }
        __syncthreads();

        #pragma unroll 4
        for (int kpl = 0; kpl < PR_CH; ++kpl) {
            ulonglong2 f01 = *reinterpret_cast<const ulonglong2*>(&sFr[kpl][rx * 4]);
            ulonglong2 f23 = *reinterpret_cast<const ulonglong2*>(&sFr[kpl][rx * 4 + 2]);
            ulonglong2 w01 = *reinterpret_cast<const ulonglong2*>(&sWo[kpl][ox * 4]);
            ulonglong2 w23 = *reinterpret_cast<const ulonglong2*>(&sWo[kpl][ox * 4 + 2]);
            u64 fr2[4] = {f01.x, f01.y, f23.x, f23.y};
            u64 wo2[4] = {w01.x, w01.y, w23.x, w23.y};
            #pragma unroll
            for (int a = 0; a < 4; ++a)
                #pragma unroll
                for (int o = 0; o < 4; ++o)
                    fma2(acc[a * 4 + o], fr2[a], wo2[o]);
        }
        __syncthreads();
    }

    // epilogue
    float bias[4];
    #pragma unroll
    for (int o = 0; o < 4; ++o) bias[o] = Woutb[ox * 4 + o];
    #pragma unroll
    for (int a = 0; a < 4; ++a) {
        float4 v;
        float* vp = reinterpret_cast<float*>(&v);
        #pragma unroll
        for (int o = 0; o < 4; ++o) {
            float2 p = unpack2(acc[a * 4 + o]);
            float z = p.x + p.y + bias[o];
            vp[o] = 1.0f / (1.0f + __expf(-z));
        }
        int row = row0 + rx * 4 + a;
        *reinterpret_cast<float4*>(preds + (size_t)row * OUT_ + ox * 4) = v;
    }
}

// ============================================================================
extern "C" void kernel_launch(void* const* d_in, const int* in_sizes, int n_in,
                              void* d_out, int out_size) {
    (void)in_sizes; (void)n_in; (void)out_size;
    const float* inp   = (const float*)d_in[0];
    const float* fr0   = (const float*)d_in[1];
    const float* noise = (const float*)d_in[2];
    const float* Winw  = (const float*)d_in[3];
    const float* Winb  = (const float*)d_in[4];
    const float* Wrecw = (const float*)d_in[5];
    const float* Wrecb = (const float*)d_in[6];
    const float* Woutw = (const float*)d_in[7];
    const float* Woutb = (const float*)d_in[8];

    float* out   = (float*)d_out;
    float* preds = out;                                   // [B,T,OUT]
    float* rates = out + (size_t)B_ * T_ * OUT_;          // [B,T,H]

    static bool attr_set = false;
    if (!attr_set) {
        cudaFuncSetAttribute(k_rnn, cudaFuncAttributeMaxDynamicSharedMemorySize,
                             SMEM_RNN);
        attr_set = true;
    }

    k_prep_x<<<(T_ * KP_IN * B_) / 256, 256>>>(inp);
    k_prep_misc<<<(H_ / 2 * B_) / 256, 256>>>(fr0, Woutw);
    k_rnn<<<NCTA, 256, SMEM_RNN>>>(noise, Winw, Winb, Wrecw, Wrecb, fr0, rates);
    k_preds<<<(B_ * T_) / 64, 256>>>(fr0, Woutb, rates, preds);
}